// round 1
// baseline (speedup 1.0000x reference)
#include <cuda_runtime.h>
#include <cuda_bf16.h>

// Problem constants (from reference)
#define B_    64
#define N_    4096
#define E_    65536
#define T_    10
#define D_    128
#define PE_   32
#define L_    4
#define TN_   (T_ + N_)                 // 4106
#define EI_   (T_ * (T_ - 1))           // 90   inner clique edges
#define EC_   (2 * T_ * N_)             // 81920 undirected cross edges
#define ETOT_ (EI_ + E_ + EC_)          // 147546 edges per graph

// Output segment sizes (flattened fp32 concat: x, pe, edge_index, edge_weight, root)
#define S_X   (B_ * TN_ * D_)           // 33,636,352
#define S_PE  (B_ * TN_ * PE_)          //  8,409,088
#define S_EI  (2 * B_ * ETOT_)          // 18,885,888
#define S_EW  (B_ * ETOT_)              //  9,442,944
#define S_RT  (B_)                      // 64

// ---------------------------------------------------------------------------
// Kernel 1: x = concat([tokens broadcast, g_x]) per batch, row-major, D=128.
// float4 vectorized: 32 float4 per row.
// ---------------------------------------------------------------------------
__global__ void k_x(const float4* __restrict__ gx,
                    const float4* __restrict__ tok,
                    float4* __restrict__ out)
{
    const int V = D_ / 4;                     // 32
    const int total = B_ * TN_ * V;           // 8,409,088
    int i = blockIdx.x * blockDim.x + threadIdx.x;
    if (i >= total) return;
    int row = i / V;
    int c   = i - row * V;
    int b   = row / TN_;
    int r   = row - b * TN_;
    float4 v;
    if (r < T_) v = tok[r * V + c];
    else        v = gx[((long long)b * N_ + (r - T_)) * V + c];
    out[i] = v;
}

// ---------------------------------------------------------------------------
// Kernel 2: pe = concat([token_pe broadcast, g_pe]) per batch, PE=32.
// ---------------------------------------------------------------------------
__global__ void k_pe(const float4* __restrict__ gpe,
                     const float4* __restrict__ tpe,
                     float4* __restrict__ out)
{
    const int V = PE_ / 4;                    // 8
    const int total = B_ * TN_ * V;           // 2,102,272
    int i = blockIdx.x * blockDim.x + threadIdx.x;
    if (i >= total) return;
    int row = i / V;
    int c   = i - row * V;
    int b   = row / TN_;
    int r   = row - b * TN_;
    float4 v;
    if (r < T_) v = tpe[r * V + c];
    else        v = gpe[((long long)b * N_ + (r - T_)) * V + c];
    out[i] = v;
}

// ---------------------------------------------------------------------------
// Kernel 3: edge_index [2, B*ETOT] as float.
// Row r, batch b, local edge k:
//   k <  90            : inner clique (i0 = k/9, jj skips diagonal)
//   k <  90+E          : g_edge_index[b, r, k-90] + T
//   else               : cross mesh; first T*N fwd (tok->node), second half rev
// All + b*TN_.
// ---------------------------------------------------------------------------
__global__ void k_ei(const int* __restrict__ gei,
                     float* __restrict__ out)
{
    int i = blockIdx.x * blockDim.x + threadIdx.x;
    if (i >= S_EI) return;
    int r = i / (B_ * ETOT_);                 // 0 or 1
    int j = i - r * (B_ * ETOT_);
    int b = j / ETOT_;
    int k = j - b * ETOT_;

    int val;
    if (k < EI_) {
        int i0 = k / (T_ - 1);
        int m  = k - i0 * (T_ - 1);
        int jj = m + (m >= i0 ? 1 : 0);
        val = (r == 0) ? i0 : jj;
    } else if (k < EI_ + E_) {
        int e = k - EI_;
        val = gei[((b * 2 + r) * E_) + e] + T_;
    } else {
        int c = k - (EI_ + E_);
        bool rev = (c >= T_ * N_);
        int c2 = rev ? (c - T_ * N_) : c;
        int t = c2 >> 12;                     // / N_ (4096)
        int n = c2 & (N_ - 1);
        int s, d;
        if (!rev) { s = t;       d = n + T_; }
        else      { s = n + T_;  d = t;      }
        val = (r == 0) ? s : d;
    }
    out[i] = (float)(val + b * TN_);
}

// ---------------------------------------------------------------------------
// Kernel 4: edge_weight [B*ETOT] + root [B].
//   k <  90      : shared_edge_weight
//   k <  90+E    : 1.0
//   else         : param[clamp(spd[b, n], 0, L)], n = (c mod T*N) mod N
// root[b] = g_root[b] + T + b*TN
// ---------------------------------------------------------------------------
__global__ void k_ew(const int* __restrict__ spd,
                     const float* __restrict__ param,
                     const float* __restrict__ shared_w,
                     const int* __restrict__ groot,
                     float* __restrict__ out_ew,
                     float* __restrict__ out_root)
{
    int i = blockIdx.x * blockDim.x + threadIdx.x;
    if (i < S_EW) {
        int b = i / ETOT_;
        int k = i - b * ETOT_;
        float w;
        if (k < EI_) {
            w = shared_w[0];
        } else if (k < EI_ + E_) {
            w = 1.0f;
        } else {
            int c  = k - (EI_ + E_);
            int c2 = (c >= T_ * N_) ? (c - T_ * N_) : c;
            int n  = c2 & (N_ - 1);
            int s  = spd[b * N_ + n];
            s = min(max(s, 0), L_);
            w = param[s];
        }
        out_ew[i] = w;
    }
    if (i < S_RT) {
        out_root[i] = (float)(groot[i] + T_ + i * TN_);
    }
}

// ---------------------------------------------------------------------------
// Launch: inputs in metadata order:
//  0 g_x [B,N,D] f32       1 g_pe [B,N,PE] f32     2 g_edge_index [B,2,E] i32
//  3 g_spd [B,N] i32       4 g_root [B] i32        5 token_list [T,D] f32
//  6 token_pe [T,PE] f32   7 shared_edge_weight f32 8 edge_weight_param [L+1] f32
// ---------------------------------------------------------------------------
extern "C" void kernel_launch(void* const* d_in, const int* in_sizes, int n_in,
                              void* d_out, int out_size)
{
    const float* g_x      = (const float*)d_in[0];
    const float* g_pe     = (const float*)d_in[1];
    const int*   g_ei     = (const int*)  d_in[2];
    const int*   g_spd    = (const int*)  d_in[3];
    const int*   g_root   = (const int*)  d_in[4];
    const float* tok      = (const float*)d_in[5];
    const float* tok_pe   = (const float*)d_in[6];
    const float* shw      = (const float*)d_in[7];
    const float* ewp      = (const float*)d_in[8];

    float* out = (float*)d_out;
    float* o_x  = out;
    float* o_pe = o_x  + S_X;
    float* o_ei = o_pe + S_PE;
    float* o_ew = o_ei + S_EI;
    float* o_rt = o_ew + S_EW;

    const int TPB = 256;

    {   // x
        int total = B_ * TN_ * (D_ / 4);
        k_x<<<(total + TPB - 1) / TPB, TPB>>>(
            (const float4*)g_x, (const float4*)tok, (float4*)o_x);
    }
    {   // pe
        int total = B_ * TN_ * (PE_ / 4);
        k_pe<<<(total + TPB - 1) / TPB, TPB>>>(
            (const float4*)g_pe, (const float4*)tok_pe, (float4*)o_pe);
    }
    {   // edge_index
        k_ei<<<(S_EI + TPB - 1) / TPB, TPB>>>(g_ei, o_ei);
    }
    {   // edge_weight + root
        k_ew<<<(S_EW + TPB - 1) / TPB, TPB>>>(g_spd, ewp, shw, g_root, o_ew, o_rt);
    }
}

// round 2
// speedup vs baseline: 1.4476x; 1.4476x over previous
#include <cuda_runtime.h>
#include <cuda_bf16.h>

// Problem constants
#define B_    64
#define N_    4096
#define E_    65536
#define T_    10
#define D_    128
#define PE_   32
#define L_    4
#define TN_   (T_ + N_)                 // 4106
#define EI_   (T_ * (T_ - 1))           // 90
#define ECH_  (T_ * N_)                 // 40960 (one direction of cross edges)
#define ETOT_ (EI_ + E_ + 2 * ECH_)     // 147546 edges per graph

// Flat fp32 output segment sizes
#define S_X   (B_ * TN_ * D_)           // 33,636,352
#define S_PE  (B_ * TN_ * PE_)          //  8,409,088
#define S_EI  (2 * B_ * ETOT_)          // 18,885,888
#define S_EW  (B_ * ETOT_)              //  9,442,944
#define S_RT  (B_)                      // 64

// float4 segment offsets
#define O1_   (S_X / 4)                 //  8,409,088  (end of x)
#define O2_   (O1_ + S_PE / 4)          // 10,511,360  (end of pe)
#define O3_   (O2_ + S_EI / 4)          // 15,232,832  (end of edge_index)
#define O4_   (O3_ + S_EW / 4)          // 17,593,568  (end of edge_weight)
#define TOT4_ (O4_ + S_RT / 4)          // 17,593,584  (end of root)

__device__ __forceinline__ int ei_val(int r, int b, int k, const int* __restrict__ gei)
{
    int val;
    if (k < EI_) {
        int i0 = k / (T_ - 1);
        int m  = k - i0 * (T_ - 1);
        int jj = m + (m >= i0 ? 1 : 0);
        val = (r == 0) ? i0 : jj;
    } else if (k < EI_ + E_) {
        val = __ldcs(&gei[(b * 2 + r) * E_ + (k - EI_)]) + T_;
    } else {
        int c   = k - (EI_ + E_);
        bool rev = (c >= ECH_);
        int c2  = rev ? (c - ECH_) : c;
        int t   = c2 >> 12;             // / N_
        int n   = c2 & (N_ - 1);
        int s, d;
        if (!rev) { s = t;      d = n + T_; }
        else      { s = n + T_; d = t;      }
        val = (r == 0) ? s : d;
    }
    return val + b * TN_;
}

__device__ __forceinline__ float ew_val(int b, int k,
                                        const int* __restrict__ spd,
                                        const float* __restrict__ param,
                                        float shw)
{
    if (k < EI_)        return shw;
    if (k < EI_ + E_)   return 1.0f;
    int c  = k - (EI_ + E_);
    int c2 = (c >= ECH_) ? (c - ECH_) : c;
    int n  = c2 & (N_ - 1);
    int s  = __ldg(&spd[b * N_ + n]);
    s = min(max(s, 0), L_);
    return __ldg(&param[s]);
}

__global__ void __launch_bounds__(256) fused_all(
    const float4* __restrict__ gx,
    const float4* __restrict__ gpe,
    const int*    __restrict__ gei,
    const int*    __restrict__ spd,
    const int*    __restrict__ groot,
    const float4* __restrict__ tok,
    const float4* __restrict__ tpe,
    const float*  __restrict__ shw,
    const float*  __restrict__ param,
    float4*       __restrict__ out)
{
    int i = blockIdx.x * blockDim.x + threadIdx.x;
    if (i >= TOT4_) return;

    if (i < O1_) {
        // ---- x segment: rows of 32 float4 (D=128)
        int row = i >> 5;
        int c   = i & 31;
        int b   = row / TN_;
        int r   = row - b * TN_;
        float4 v;
        if (r < T_) v = __ldg(&tok[r * 32 + c]);
        else        v = __ldcs(&gx[((long long)b * N_ + (r - T_)) * 32 + c]);
        __stcs(&out[i], v);
    } else if (i < O2_) {
        // ---- pe segment: rows of 8 float4 (PE=32)
        int p   = i - O1_;
        int row = p >> 3;
        int c   = p & 7;
        int b   = row / TN_;
        int r   = row - b * TN_;
        float4 v;
        if (r < T_) v = __ldg(&tpe[r * 8 + c]);
        else        v = __ldcs(&gpe[((long long)b * N_ + (r - T_)) * 8 + c]);
        __stcs(&out[i], v);
    } else if (i < O3_) {
        // ---- edge_index segment: 4 scalars per thread.
        // Group of 4 never straddles the r boundary (B_*ETOT_ % 4 == 0).
        int q = (i - O2_) << 2;
        int r = q / (B_ * ETOT_);
        int j0 = q - r * (B_ * ETOT_);
        float4 v;
        #pragma unroll
        for (int u = 0; u < 4; u++) {
            int j = j0 + u;
            int b = j / ETOT_;
            int k = j - b * ETOT_;
            ((float*)&v)[u] = (float)ei_val(r, b, k, gei);
        }
        __stcs(&out[i], v);
    } else if (i < O4_) {
        // ---- edge_weight segment
        int s0 = (i - O3_) << 2;
        float shv = __ldg(shw);
        float4 v;
        #pragma unroll
        for (int u = 0; u < 4; u++) {
            int j = s0 + u;
            int b = j / ETOT_;
            int k = j - b * ETOT_;
            ((float*)&v)[u] = ew_val(b, k, spd, param, shv);
        }
        __stcs(&out[i], v);
    } else {
        // ---- root segment (16 float4)
        int r0 = (i - O4_) << 2;
        float4 v;
        #pragma unroll
        for (int u = 0; u < 4; u++) {
            int b = r0 + u;
            ((float*)&v)[u] = (float)(__ldg(&groot[b]) + T_ + b * TN_);
        }
        __stcs(&out[i], v);
    }
}

extern "C" void kernel_launch(void* const* d_in, const int* in_sizes, int n_in,
                              void* d_out, int out_size)
{
    const float4* g_x    = (const float4*)d_in[0];
    const float4* g_pe   = (const float4*)d_in[1];
    const int*    g_ei   = (const int*)   d_in[2];
    const int*    g_spd  = (const int*)   d_in[3];
    const int*    g_root = (const int*)   d_in[4];
    const float4* tok    = (const float4*)d_in[5];
    const float4* tok_pe = (const float4*)d_in[6];
    const float*  shw    = (const float*) d_in[7];
    const float*  ewp    = (const float*) d_in[8];

    const int TPB = 256;
    int blocks = (TOT4_ + TPB - 1) / TPB;   // 68,725
    fused_all<<<blocks, TPB>>>(g_x, g_pe, g_ei, g_spd, g_root,
                               tok, tok_pe, shw, ewp, (float4*)d_out);
}